// round 9
// baseline (speedup 1.0000x reference)
#include <cuda_runtime.h>
#include <math.h>

// Problem constants (fixed by setup_inputs): N=16, T=2048, D=2
#define TT 2048
#define NBMAX 16
#define LOG2PI_F 1.8378770664093453f
#define LN2F     0.6931471805599453f

// Scratch (device globals; no allocation allowed)
__device__ float4 g_pack[NBMAX * TT];   // (A_j, xs_j, ys_j, 0)
__device__ float  g_logP[NBMAX * TT];   // log( sum_{j<i} exp(t_j/sp) )

__device__ __forceinline__ float ex2f(float x) {
    float r;
    asm("ex2.approx.f32 %0, %1;" : "=f"(r) : "f"(x));
    return r;
}

// ---------------------------------------------------------------------------
// Kernel A: per batch, build packed per-j data and prefix logP.
//   c2_j = t_j / (sp * ln2)            (log2 domain)
//   A_j  = c2_j - h2l*(xj^2+yj^2)
//   xs_j = 2*h2l*xj ; ys_j = 2*h2l*yj
//   E_j  = 2^{c2_j};  P_i = sum_{j<i} E_j ; g_logP[i] = ln(P_i)
// ---------------------------------------------------------------------------
__global__ void prep_kernel(const float* __restrict__ tim,
                            const float* __restrict__ loc,
                            const float* __restrict__ cd_p,
                            const float* __restrict__ sls_p) {
    const int n   = blockIdx.x;
    const int tid = threadIdx.x;           // 256 threads
    const float cd  = *cd_p;
    const float sls = *sls_p;
    const float sp  = log1pf(__expf(cd));          // softplus(coeff_decay)
    const float rc2 = 1.0f / (sp * LN2F);
    const float h2l = 0.5f * __expf(-2.0f * sls) / LN2F;

    __shared__ float sE[TT];
    __shared__ float wtot[8];
    __shared__ float wbase[8];

    for (int j = tid; j < TT; j += 256) {
        float tj = tim[n * TT + j];
        float xj = loc[(n * TT + j) * 2 + 0];
        float yj = loc[(n * TT + j) * 2 + 1];
        float c2 = tj * rc2;
        float A  = fmaf(-h2l, fmaf(xj, xj, yj * yj), c2);
        float xs = 2.0f * h2l * xj;
        float ys = 2.0f * h2l * yj;
        g_pack[n * TT + j] = make_float4(A, xs, ys, 0.0f);
        sE[j] = ex2f(c2);
    }
    __syncthreads();

    const int C = TT / 256;                // 8
    float part = 0.0f;
#pragma unroll
    for (int kk = 0; kk < C; kk++) part += sE[tid * C + kk];

    float inc = part;
    const int lane = tid & 31;
#pragma unroll
    for (int o = 1; o < 32; o <<= 1) {
        float v = __shfl_up_sync(0xffffffffu, inc, o);
        if (lane >= o) inc += v;
    }
    if (lane == 31) wtot[tid >> 5] = inc;
    __syncthreads();
    if (tid < 8) {
        float v = wtot[tid], s = v;
#pragma unroll
        for (int o = 1; o < 8; o <<= 1) {
            float u = __shfl_up_sync(0x000000ffu, s, o);
            if (tid >= o) s += u;
        }
        wbase[tid] = s - v;
    }
    __syncthreads();

    float run = wbase[tid >> 5] + (inc - part);
#pragma unroll
    for (int kk = 0; kk < C; kk++) {
        int j = tid * C + kk;
        g_logP[n * TT + j] = (j == 0) ? 0.0f : __logf(run);
        run += sE[j];
    }
}

// ---------------------------------------------------------------------------
// Kernel B: block = (batch n, slice k of 8). Warp w owns ONE whole tile:
//   w<4 : k + 8w            w>=4: 63 - k - 8(w-4)
// SMSP s carries wid s and s+4: 32(k+8s) + 32(63-k-8s) = 2016 j  (uniform).
// The ENTIRE per-batch j-stream (2048 float4 = 32KB) is staged into smem
// once; after a single __syncthreads every warp free-runs its own dense
// range + predicated triangular tail with NO further barriers. Epilogue is
// warp-private (lane owns row i = 32*tile + lane).
// Grid = 16*8 = 128 blocks -> one wave, one block per SM.
// ---------------------------------------------------------------------------
__global__ void __launch_bounds__(256, 1)
main_kernel(const float* __restrict__ loc,
            const float* __restrict__ mu0_p,
            const float* __restrict__ ls0_p,
            const float* __restrict__ sls_p,
            float* __restrict__ out) {
    const int b    = blockIdx.x;
    const int n    = b >> 3;               // batch
    const int k    = b & 7;                // slice
    const int tid  = threadIdx.x;
    const int wid  = tid >> 5;
    const int lane = tid & 31;

    const int tile = (wid < 4) ? (k + (wid << 3))
                               : (63 - k - ((wid - 4) << 3));

    __shared__ float4 sj[TT];              // 32KB: whole batch j-stream

    const float sls = *sls_p;
    const float h2l = 0.5f * __expf(-2.0f * sls) / LN2F;

    const int i = (tile << 5) + lane;
    const float xi = loc[(n * TT + i) * 2 + 0];
    const float yi = loc[(n * TT + i) * 2 + 1];

    const float4* __restrict__ pk = &g_pack[n * TT];

    // Stage the full 2048-entry stream (8 independent LDG.128 per thread)
#pragma unroll
    for (int t = 0; t < TT / 256; t++)
        sj[t * 256 + tid] = pk[t * 256 + tid];
    __syncthreads();                       // the ONLY barrier

    // Dense range [0, 32*tile), multiple of 32 -> unroll 8, no remainder
    const int lim = tile << 5;
    float s0 = 0.0f, s1 = 0.0f, s2 = 0.0f, s3 = 0.0f;
    for (int jl = 0; jl < lim; jl += 8) {
        float4 p0 = sj[jl + 0]; float4 p1 = sj[jl + 1];
        float4 p2 = sj[jl + 2]; float4 p3 = sj[jl + 3];
        float4 p4 = sj[jl + 4]; float4 p5 = sj[jl + 5];
        float4 p6 = sj[jl + 6]; float4 p7 = sj[jl + 7];
        s0 += ex2f(fmaf(xi, p0.y, fmaf(yi, p0.z, p0.x)));
        s1 += ex2f(fmaf(xi, p1.y, fmaf(yi, p1.z, p1.x)));
        s2 += ex2f(fmaf(xi, p2.y, fmaf(yi, p2.z, p2.x)));
        s3 += ex2f(fmaf(xi, p3.y, fmaf(yi, p3.z, p3.x)));
        s0 += ex2f(fmaf(xi, p4.y, fmaf(yi, p4.z, p4.x)));
        s1 += ex2f(fmaf(xi, p5.y, fmaf(yi, p5.z, p5.x)));
        s2 += ex2f(fmaf(xi, p6.y, fmaf(yi, p6.z, p6.x)));
        s3 += ex2f(fmaf(xi, p7.y, fmaf(yi, p7.z, p7.x)));
    }

    // Triangular tail: j = 32*tile + jt, active for lanes with jt < lane
    {
        const int base = tile << 5;
#pragma unroll
        for (int jt = 0; jt < 31; jt++) {
            float4 q = sj[base + jt];
            float e = ex2f(fmaf(xi, q.y, fmaf(yi, q.z, q.x)));
            s1 += (jt < lane) ? e : 0.0f;
        }
    }

    // Warp-private epilogue
    float res;
    if (i == 0) {
        const float mu0 = *mu0_p;
        const float ls0 = *ls0_p;
        const float iv  = __expf(-2.0f * ls0);
        const float dx = xi - mu0, dy = yi - mu0;
        res = -0.5f * iv * fmaf(dx, dx, dy * dy) - 2.0f * ls0 - LOG2PI_F;
    } else {
        const float S  = (s0 + s1) + (s2 + s3);
        const float B2 = -h2l * fmaf(xi, xi, yi * yi);
        const float K  = 2.0f * sls + LOG2PI_F;
        res = __logf(S) + LN2F * B2 - K - g_logP[n * TT + i];
    }
    out[n * TT + i] = res;
}

// ---------------------------------------------------------------------------
extern "C" void kernel_launch(void* const* d_in, const int* in_sizes, int n_in,
                              void* d_out, int out_size) {
    const float* tim  = (const float*)d_in[0];  // (N, T, 1)
    const float* loc  = (const float*)d_in[1];  // (N, T, 2)
    const float* mu0  = (const float*)d_in[2];
    const float* ls0  = (const float*)d_in[3];
    const float* cd   = (const float*)d_in[4];
    const float* sls  = (const float*)d_in[5];
    float* out = (float*)d_out;

    const int N = in_sizes[0] / TT;             // 16

    prep_kernel<<<N, 256>>>(tim, loc, cd, sls);
    main_kernel<<<N * 8, 256>>>(loc, mu0, ls0, sls, out);
}